// round 6
// baseline (speedup 1.0000x reference)
#include <cuda_runtime.h>
#include <cstdint>

#define KS 93          // gaussian kernel size (static, matches reference)
#define NPTS 256       // points per batch
#define W_OUT 512
#define H_OUT 512
#define RPB 8          // rows per block (4 packed f32x2 accumulators)
#define SLABW 128      // columns per block (one per thread)
#define NT 128         // threads per block
#define PAD 127        // left zero-padding of the gaussian table
#define GNP_LEN 348    // nonzero only in [PAD, PAD+93); t+dd <= 127+219 = 346

// One block per (batch, 8-row group, 128-col slab).  grid = 8*64*4 = 2048.
// Thread t owns column colBase+t for 8 rows, accumulated as 4 f32x2 pairs.
__global__ __launch_bounds__(NT, 14)
void density_kernel(const float* __restrict__ labels,
                    const float* __restrict__ sigma_ptr,
                    float* __restrict__ out) {
    const int slab    = blockIdx.x & 3;
    const int rowBase = ((blockIdx.x >> 2) & 63) * RPB;
    const int b       = blockIdx.x >> 8;
    const int colBase = slab * SLABW;
    const int t    = threadIdx.x;
    const int warp = t >> 5;
    const int lane = t & 31;

    __shared__ __align__(16) float  sW[NPTS][RPB];   // 8 row-weights per active point
    __shared__ __align__(8)  float2 gnp2[GNP_LEN];   // duplicated-pair gaussian, zero-padded
    __shared__ int   sD[NPTS];                       // PAD + colBase - C0 per active point
    __shared__ float wsum[4];
    __shared__ int   warpCnt[8];                     // 4 warps x 2 passes

    // ---- Kick off global loads early (overlap with setup math) -----------
    const float2* lab = (const float2*)(labels + (size_t)b * NPTS * 2);
    const float2 pa = lab[t];                        // (row-coord, col-coord)
    const float2 pb = lab[t + NT];
    const float s = fabsf(sigma_ptr[0]);

    // ---- Gaussian setup (per block; deterministic) -----------------------
    const float inv2s2 = 1.0f / (2.0f * s * s);
    float gval = 0.0f;
    if (t < KS) {
        const float a = (float)(t - KS / 2);         // [-46, 46]
        gval = expf(-(a * a) * inv2s2);
    }
    float v = gval;
    #pragma unroll
    for (int off = 16; off > 0; off >>= 1) v += __shfl_down_sync(0xffffffffu, v, off);
    if (lane == 0) wsum[warp] = v;

    // ---- Classification (independent of gaussian table) ------------------
    // row window: da = rowBase - trunc(l0 - 46.5); active iff da in [-7, 92]
    const int da = rowBase - (int)truncf(pa.x - 46.5f);
    const int db = rowBase - (int)truncf(pb.x - 46.5f);
    // col window: dc = colBase - trunc(l1 - 46.5); slab hit iff dc in [-127, 92]
    const int dca = colBase - (int)truncf(pa.y - 46.5f);
    const int dcb = colBase - (int)truncf(pb.y - 46.5f);
    const bool actA = ((unsigned)(da + RPB - 1) < (unsigned)(KS + RPB - 1)) &&
                      ((unsigned)(dca + PAD)    < (unsigned)(KS + PAD));
    const bool actB = ((unsigned)(db + RPB - 1) < (unsigned)(KS + RPB - 1)) &&
                      ((unsigned)(dcb + PAD)    < (unsigned)(KS + PAD));
    const unsigned balA = __ballot_sync(0xffffffffu, actA);
    const unsigned balB = __ballot_sync(0xffffffffu, actB);
    if (lane == 0) {
        warpCnt[warp]     = __popc(balA);
        warpCnt[4 + warp] = __popc(balB);
    }

    // zero-fill the padded pair table
    #pragma unroll
    for (int i = t; i < GNP_LEN; i += NT) gnp2[i] = make_float2(0.0f, 0.0f);
    __syncthreads();                                 // wsum + zeros + warpCnt visible

    // normalized gaussian into the pair table
    const float total = wsum[0] + wsum[1] + wsum[2] + wsum[3];
    if (t < KS) {
        const float g = gval / total;
        gnp2[PAD + t] = make_float2(g, g);
    }

    // compact-list prefix offsets
    int M = 0;
    #pragma unroll
    for (int i = 0; i < 8; i++) M += warpCnt[i];
    int baseA = 0;
    for (int i = 0; i < warp; i++) baseA += warpCnt[i];
    int baseB = 0;
    for (int i = 0; i < 4 + warp; i++) baseB += warpCnt[i];
    __syncthreads();                                 // gnp2 table complete

    const unsigned ltmask = (1u << lane) - 1u;
    if (actA) {
        const int pos = baseA + __popc(balA & ltmask);
        sD[pos] = PAD + dca;
        #pragma unroll
        for (int r = 0; r < RPB; r++)                // zeros come free from padding
            sW[pos][r] = gnp2[PAD + da + r].x;
    }
    if (actB) {
        const int pos = baseB + __popc(balB & ltmask);
        sD[pos] = PAD + dcb;
        #pragma unroll
        for (int r = 0; r < RPB; r++)
            sW[pos][r] = gnp2[PAD + db + r].x;
    }
    __syncthreads();                                 // compact list complete

    // ---- Phase 2: packed f32x2 accumulation over compact list (~21 pts) --
    uint64_t acc0 = 0ull, acc1 = 0ull, acc2 = 0ull, acc3 = 0ull;

    #pragma unroll 4
    for (int m = 0; m < M; m++) {
        const int dd = sD[m];                        // broadcast LDS
        const ulonglong2* wp = (const ulonglong2*)&sW[m][0];
        const ulonglong2 w01 = wp[0];                // rows 0-3 (two packed pairs)
        const ulonglong2 w23 = wp[1];                // rows 4-7
        const uint64_t gv2 = *(const uint64_t*)&gnp2[t + dd];  // LDS.64, {gv, gv}
        asm("fma.rn.f32x2 %0, %1, %2, %0;" : "+l"(acc0) : "l"(gv2), "l"(w01.x));
        asm("fma.rn.f32x2 %0, %1, %2, %0;" : "+l"(acc1) : "l"(gv2), "l"(w01.y));
        asm("fma.rn.f32x2 %0, %1, %2, %0;" : "+l"(acc2) : "l"(gv2), "l"(w23.x));
        asm("fma.rn.f32x2 %0, %1, %2, %0;" : "+l"(acc3) : "l"(gv2), "l"(w23.y));
    }

    // ---- Write 8 rows x 128 cols, coalesced ------------------------------
    float* o = out + ((size_t)b * H_OUT + rowBase) * W_OUT + colBase;
    uint32_t lo, hi;
    asm("mov.b64 {%0, %1}, %2;" : "=r"(lo), "=r"(hi) : "l"(acc0));
    o[0 * W_OUT + t] = __uint_as_float(lo);
    o[1 * W_OUT + t] = __uint_as_float(hi);
    asm("mov.b64 {%0, %1}, %2;" : "=r"(lo), "=r"(hi) : "l"(acc1));
    o[2 * W_OUT + t] = __uint_as_float(lo);
    o[3 * W_OUT + t] = __uint_as_float(hi);
    asm("mov.b64 {%0, %1}, %2;" : "=r"(lo), "=r"(hi) : "l"(acc2));
    o[4 * W_OUT + t] = __uint_as_float(lo);
    o[5 * W_OUT + t] = __uint_as_float(hi);
    asm("mov.b64 {%0, %1}, %2;" : "=r"(lo), "=r"(hi) : "l"(acc3));
    o[6 * W_OUT + t] = __uint_as_float(lo);
    o[7 * W_OUT + t] = __uint_as_float(hi);
}

extern "C" void kernel_launch(void* const* d_in, const int* in_sizes, int n_in,
                              void* d_out, int out_size) {
    // metadata order: [0] batch_images (unused by the math),
    //                 [1] batch_labels [8,256,2] f32, [2] sigma scalar f32
    const float* labels = (const float*)d_in[1];
    const float* sigma  = (const float*)d_in[2];
    float* out = (float*)d_out;                   // [8,1,512,512] f32

    density_kernel<<<8 * (H_OUT / RPB) * (W_OUT / SLABW), NT>>>(labels, sigma, out);
}